// round 5
// baseline (speedup 1.0000x reference)
#include <cuda_runtime.h>
#include <cuda_bf16.h>
#include <math.h>

// Problem constants (fixed by the reference)
#define GM 50000        // nodes
#define GK 3703         // input dim
#define GN 256          // hidden dim
#define GE 400000       // edges
#define GO 6            // output classes

// ---------------- scratch (static device memory; no allocation) ----------------
__device__ __align__(16) float g_support1[(size_t)GM * GN];  // X @ W1    (51.2 MB)
__device__ __align__(16) float g_support2[(size_t)GM * GO];  // h1 @ W2   (1.2 MB)
__device__ int   g_deg[GM];
__device__ int   g_cur[GM];
__device__ int   g_off[GM + 1];
__device__ int   g_ssrc[GE];
__device__ float g_sw[GE];

// ---------------- helpers ----------------
__device__ __forceinline__ unsigned f2tf32(float f) {
    unsigned u;
    asm("cvt.rna.tf32.f32 %0, %1;" : "=r"(u) : "f"(f));
    return u;
}

__device__ __forceinline__ void mma_tf32(float* c, const unsigned* a, const unsigned* b) {
    asm volatile(
        "mma.sync.aligned.m16n8k8.row.col.f32.tf32.tf32.f32 "
        "{%0,%1,%2,%3}, {%4,%5,%6,%7}, {%8,%9}, {%0,%1,%2,%3};"
        : "+f"(c[0]), "+f"(c[1]), "+f"(c[2]), "+f"(c[3])
        : "r"(a[0]), "r"(a[1]), "r"(a[2]), "r"(a[3]),
          "r"(b[0]), "r"(b[1]));
}

// ---------------- edge preprocessing ----------------
__global__ void zero_kernel() {
    int i = blockIdx.x * blockDim.x + threadIdx.x;
    if (i < GM) { g_deg[i] = 0; g_cur[i] = 0; }
}

__global__ void hist_kernel(const int* __restrict__ dst) {
    int e = blockIdx.x * blockDim.x + threadIdx.x;
    if (e < GE) atomicAdd(&g_deg[dst[e]], 1);
}

// single-block exclusive prefix sum over g_deg -> g_off
__global__ void scan_kernel() {
    __shared__ int sh[1024];
    const int t = threadIdx.x;
    const int CH = 49;                 // 1024*49 = 50176 >= 50000
    int base = t * CH;
    int s = 0;
    #pragma unroll 7
    for (int i = 0; i < CH; i++) {
        int idx = base + i;
        if (idx < GM) s += g_deg[idx];
    }
    sh[t] = s;
    __syncthreads();
    for (int off = 1; off < 1024; off <<= 1) {
        int v = 0;
        if (t >= off) v = sh[t - off];
        __syncthreads();
        if (t >= off) sh[t] += v;
        __syncthreads();
    }
    int run = (t == 0) ? 0 : sh[t - 1];   // exclusive prefix of this chunk
    for (int i = 0; i < CH; i++) {
        int idx = base + i;
        if (idx < GM) { g_off[idx] = run; run += g_deg[idx]; }
    }
    if (t == 1023) g_off[GM] = sh[1023];
}

__global__ void bucket_kernel(const int* __restrict__ src,
                              const int* __restrict__ dst,
                              const float* __restrict__ w) {
    int e = blockIdx.x * blockDim.x + threadIdx.x;
    if (e < GE) {
        int d = dst[e];
        int r = atomicAdd(&g_cur[d], 1);
        int p = g_off[d] + r;
        g_ssrc[p] = src[e];
        g_sw[p]   = w[e];
    }
}

// ---------------- GEMM1: support1 = tf32(X) @ tf32(W1), fp32 accumulate ----------------
// Block tile 128x128, BK=16, 8 warps (4x2), warp tile 32x64, m16n8k8 tf32 MMA.
__global__ __launch_bounds__(256, 2)
void gemm1_kernel(const float* __restrict__ x, const float* __restrict__ W1) {
    __shared__ unsigned As[16][136];   // [k][m], stride 136 (8 mod 32) -> conflict-free frag reads
    __shared__ unsigned Bs[16][136];   // [k][n]

    const int tid  = threadIdx.x;
    const int m0   = blockIdx.y * 128;
    const int n0   = blockIdx.x * 128;
    const int wid  = tid >> 5, lane = tid & 31;
    const int wm   = wid & 3,  wn   = wid >> 2;
    const int g    = lane >> 2, tg  = lane & 3;

    float acc[2][8][4];
    #pragma unroll
    for (int a = 0; a < 2; a++)
        #pragma unroll
        for (int b = 0; b < 8; b++)
            #pragma unroll
            for (int i = 0; i < 4; i++) acc[a][b][i] = 0.f;

    const int KB = (GK + 15) / 16;     // 232
    unsigned aval[8], bval[8];

    // prologue loads (kb = 0)
    {
        const int k0 = 0;
        #pragma unroll
        for (int i = 0; i < 8; i++) {
            int e = tid + i * 256; int r = e >> 4, c = e & 15;
            int gr = m0 + r, gc = k0 + c;
            float v = (gr < GM && gc < GK) ? x[gr * GK + gc] : 0.f;
            aval[i] = f2tf32(v);
        }
        #pragma unroll
        for (int i = 0; i < 8; i++) {
            int e = tid + i * 256; int kr = e >> 7, nc = e & 127;
            int gk = k0 + kr;
            float v = (gk < GK) ? W1[gk * GN + n0 + nc] : 0.f;
            bval[i] = f2tf32(v);
        }
    }

    for (int kb = 0; kb < KB; kb++) {
        __syncthreads();   // previous compute finished
        #pragma unroll
        for (int i = 0; i < 8; i++) {
            int e = tid + i * 256;
            As[e & 15][e >> 4] = aval[i];
        }
        #pragma unroll
        for (int i = 0; i < 8; i++) {
            int e = tid + i * 256;
            Bs[e >> 7][e & 127] = bval[i];
        }
        __syncthreads();

        // prefetch next tile's globals (overlaps with compute)
        if (kb + 1 < KB) {
            const int k0 = (kb + 1) * 16;
            #pragma unroll
            for (int i = 0; i < 8; i++) {
                int e = tid + i * 256; int r = e >> 4, c = e & 15;
                int gr = m0 + r, gc = k0 + c;
                float v = (gr < GM && gc < GK) ? x[gr * GK + gc] : 0.f;
                aval[i] = f2tf32(v);
            }
            #pragma unroll
            for (int i = 0; i < 8; i++) {
                int e = tid + i * 256; int kr = e >> 7, nc = e & 127;
                int gk = k0 + kr;
                float v = (gk < GK) ? W1[gk * GN + n0 + nc] : 0.f;
                bval[i] = f2tf32(v);
            }
        }

        // compute: 2 k-steps of 8
        #pragma unroll
        for (int ks = 0; ks < 16; ks += 8) {
            unsigned af[2][4];
            #pragma unroll
            for (int mt = 0; mt < 2; mt++) {
                int mr = wm * 32 + mt * 16 + g;
                af[mt][0] = As[ks + tg    ][mr];
                af[mt][1] = As[ks + tg    ][mr + 8];
                af[mt][2] = As[ks + tg + 4][mr];
                af[mt][3] = As[ks + tg + 4][mr + 8];
            }
            unsigned bf[8][2];
            #pragma unroll
            for (int nt = 0; nt < 8; nt++) {
                int col = wn * 64 + nt * 8 + g;
                bf[nt][0] = Bs[ks + tg    ][col];
                bf[nt][1] = Bs[ks + tg + 4][col];
            }
            #pragma unroll
            for (int mt = 0; mt < 2; mt++)
                #pragma unroll
                for (int nt = 0; nt < 8; nt++)
                    mma_tf32(acc[mt][nt], af[mt], bf[nt]);
        }
    }

    // epilogue: raw support (bias added post-aggregation)
    #pragma unroll
    for (int mt = 0; mt < 2; mt++) {
        int r0 = m0 + wm * 32 + mt * 16 + g;
        int r1 = r0 + 8;
        #pragma unroll
        for (int nt = 0; nt < 8; nt++) {
            int col = n0 + wn * 64 + nt * 8 + 2 * tg;
            if (r0 < GM) {
                float2 v; v.x = acc[mt][nt][0]; v.y = acc[mt][nt][1];
                *reinterpret_cast<float2*>(&g_support1[(size_t)r0 * GN + col]) = v;
            }
            if (r1 < GM) {
                float2 v; v.x = acc[mt][nt][2]; v.y = acc[mt][nt][3];
                *reinterpret_cast<float2*>(&g_support1[(size_t)r1 * GN + col]) = v;
            }
        }
    }
}

// ---------------- layer-1 aggregation fused with +b1, leaky_relu, @W2 ----------------
// One warp per node (32 lanes x 8 channels), 8 nodes per 256-thread block.
__global__ __launch_bounds__(256)
void agg1_kernel(const float* __restrict__ b1, const float* __restrict__ W2) {
    __shared__ float sW2[GN * GO];   // 1536 floats
    __shared__ float sb1[GN];
    const int t = threadIdx.x;
    for (int i = t; i < GN * GO; i += 256) sW2[i] = W2[i];
    if (t < GN) sb1[t] = b1[t];
    __syncthreads();

    const int lane = t & 31;
    const int sub  = t >> 5;
    const int v    = blockIdx.x * 8 + sub;   // grid = 6250 -> exactly 50000

    float4 a0 = make_float4(0.f, 0.f, 0.f, 0.f);
    float4 a1 = make_float4(0.f, 0.f, 0.f, 0.f);
    const int beg = g_off[v], end = g_off[v + 1];
    for (int e = beg; e < end; e++) {
        int s = g_ssrc[e];
        float w = g_sw[e];
        const float4* row = reinterpret_cast<const float4*>(g_support1 + (size_t)s * GN);
        float4 p0 = row[lane * 2];
        float4 p1 = row[lane * 2 + 1];
        a0.x += p0.x * w; a0.y += p0.y * w; a0.z += p0.z * w; a0.w += p0.w * w;
        a1.x += p1.x * w; a1.y += p1.y * w; a1.z += p1.z * w; a1.w += p1.w * w;
    }

    const int cb = lane * 8;
    float h[8];
    h[0] = a0.x + sb1[cb + 0]; h[1] = a0.y + sb1[cb + 1];
    h[2] = a0.z + sb1[cb + 2]; h[3] = a0.w + sb1[cb + 3];
    h[4] = a1.x + sb1[cb + 4]; h[5] = a1.y + sb1[cb + 5];
    h[6] = a1.z + sb1[cb + 6]; h[7] = a1.w + sb1[cb + 7];
    #pragma unroll
    for (int i = 0; i < 8; i++) h[i] = (h[i] > 0.f) ? h[i] : 0.01f * h[i];

    float p[GO];
    #pragma unroll
    for (int j = 0; j < GO; j++) p[j] = 0.f;
    #pragma unroll
    for (int i = 0; i < 8; i++) {
        const float* wr = &sW2[(cb + i) * GO];
        #pragma unroll
        for (int j = 0; j < GO; j++) p[j] += h[i] * wr[j];
    }
    #pragma unroll
    for (int j = 0; j < GO; j++)
        #pragma unroll
        for (int o = 16; o > 0; o >>= 1)
            p[j] += __shfl_xor_sync(0xffffffffu, p[j], o);

    if (lane < GO) g_support2[(size_t)v * GO + lane] = p[lane];
}

// ---------------- layer-2 aggregation + b2 + log_softmax ----------------
__global__ void agg2_kernel(const float* __restrict__ b2, float* __restrict__ out) {
    int v = blockIdx.x * blockDim.x + threadIdx.x;
    if (v >= GM) return;
    float a[GO];
    #pragma unroll
    for (int j = 0; j < GO; j++) a[j] = 0.f;
    const int beg = g_off[v], end = g_off[v + 1];
    for (int e = beg; e < end; e++) {
        int s = g_ssrc[e];
        float w = g_sw[e];
        const float* r = g_support2 + (size_t)s * GO;
        #pragma unroll
        for (int j = 0; j < GO; j++) a[j] += __ldg(r + j) * w;
    }
    float l[GO];
    #pragma unroll
    for (int j = 0; j < GO; j++) l[j] = a[j] + b2[j];
    float m = l[0];
    #pragma unroll
    for (int j = 1; j < GO; j++) m = fmaxf(m, l[j]);
    float sum = 0.f;
    #pragma unroll
    for (int j = 0; j < GO; j++) sum += expf(l[j] - m);
    float ls = logf(sum);
    #pragma unroll
    for (int j = 0; j < GO; j++) out[(size_t)v * GO + j] = l[j] - m - ls;
}

// ---------------- launch ----------------
extern "C" void kernel_launch(void* const* d_in, const int* in_sizes, int n_in,
                              void* d_out, int out_size) {
    const float* x    = (const float*)d_in[0];
    const int*   esrc = (const int*)  d_in[1];
    const int*   edst = (const int*)  d_in[2];
    const float* ew   = (const float*)d_in[3];
    const float* W1   = (const float*)d_in[4];
    const float* b1   = (const float*)d_in[5];
    const float* W2   = (const float*)d_in[6];
    const float* b2   = (const float*)d_in[7];
    float* out = (float*)d_out;

    // edge preprocessing (counting sort by dst)
    zero_kernel  <<<(GM + 255) / 256, 256>>>();
    hist_kernel  <<<(GE + 255) / 256, 256>>>(edst);
    scan_kernel  <<<1, 1024>>>();
    bucket_kernel<<<(GE + 255) / 256, 256>>>(esrc, edst, ew);

    // dense transform (dominant cost)
    dim3 ggrid(2, (GM + 127) / 128);   // n-tiles inner -> adjacent blocks share X via L2
    gemm1_kernel<<<ggrid, 256>>>(x, W1);

    // sparse agg 1 (+b1, leaky_relu, @W2 fused)
    agg1_kernel<<<GM / 8, 256>>>(b1, W2);

    // sparse agg 2 (+b2, log_softmax)
    agg2_kernel<<<(GM + 127) / 128, 128>>>(b2, out);
}